// round 7
// baseline (speedup 1.0000x reference)
#include <cuda_runtime.h>

// Problem constants (fixed by the reference setup_inputs)
#define B   16
#define C   85
#define H   128
#define W   128
#define HW  (H * W)        // 16384
#define NT  64             // targets per image
#define NC  80             // num classes = C - 5
#define NCH 81             // channels 4..84 (obj + cls)

#define THREADS    256
#define ITERS      18
#define BX         72                   // blocks per batch: 72*256*18 == 331776 f4
#define BLOCKS     (BX * B)             // 1152 total, single wave

#define CH_F4      (HW / 4)             // 4096 float4 per channel
#define PER_B_F4   (NCH * CH_F4)        // 331776 float4 per batch image (ch 4..84)
#define STRIDE_F4  (BX * THREADS)       // 18432 f4 per iteration step (per batch)

// Global accumulators + completion counter. Zero at module load; the last
// block of every launch resets them, so each launch / graph replay starts clean.
// [0] = sum softplus(obj channel)
// [1] = sum softplus(cls channels)
// [2] = sum (1 - iou) box loss
// [3] = obj correction: sum of x_obj at unique assigned cells
// [4] = cls correction: sum of x_cls at unique (cell, cls) pairs
__device__ double        g_acc[5];
__device__ unsigned int  g_done;

// softplus(x) = max(x,0) + ln(1 + exp(-|x|)).
// u = exp(-|x|) via single MUFU.EX2; ln(1+u) on u in [0,1] via degree-5
// Chebyshev-economized polynomial (max abs err ~9e-6). Only 1 MUFU/element.
__device__ __forceinline__ float softplus_f(float x) {
    const float u = __expf(-fabsf(x));
    float p = fmaf(0.030401920f, u, -0.131407840f);
    p = fmaf(p, u,  0.285051320f);
    p = fmaf(p, u, -0.490108524f);
    p = fmaf(p, u,  0.999206690f);
    p = fmaf(p, u,  0.000012223f);
    return fmaxf(x, 0.0f) + p;
}

__global__ __launch_bounds__(THREADS) void fused_kernel(const float* __restrict__ preds,
                                                        const float* __restrict__ tg,
                                                        float* __restrict__ out) {
    const int bx  = blockIdx.x;          // 0..71  position within batch
    const int b   = blockIdx.y;          // 0..15  batch image
    const int tid = threadIdx.x;

    __shared__ float sh[2 * THREADS];
    __shared__ float sh2[8];
    __shared__ int   s_key[NT];          // packed (idx<<7 | cls) per target

    // ---------- bulk softplus sweep over channels 4..84 of batch b ----------
    // base of channel 4 for this image, in float4 units
    const float4* __restrict__ p4 =
        reinterpret_cast<const float4*>(preds) + ((size_t)b * C + 4) * CH_F4;

    const int g0 = bx * THREADS + tid;   // 0..18431

    float obj_acc = 0.0f;
    float cls_acc = 0.0f;

#pragma unroll
    for (int i = 0; i < ITERS; i++) {
        const float4 v = p4[g0 + i * STRIDE_F4];           // plain cached load
        const float  s = softplus_f(v.x) + softplus_f(v.y)
                       + softplus_f(v.z) + softplus_f(v.w);
        // obj channel (ch 4) occupies the first CH_F4=4096 f4 => i==0 && bx<16
        if (i == 0 && bx < 16) obj_acc += s;
        else                   cls_acc += s;
    }

    // block reduce both accumulators
    sh[tid]           = obj_acc;
    sh[tid + THREADS] = cls_acc;
    __syncthreads();
#pragma unroll
    for (int s = THREADS / 2; s > 32; s >>= 1) {
        if (tid < s) {
            sh[tid]           += sh[tid + s];
            sh[tid + THREADS] += sh[tid + THREADS + s];
        }
        __syncthreads();
    }
    if (tid < 32) {
        float vo = sh[tid] + sh[tid + 32];
        float vc = sh[tid + THREADS] + sh[tid + THREADS + 32];
#pragma unroll
        for (int o = 16; o > 0; o >>= 1) {
            vo += __shfl_down_sync(0xffffffffu, vo, o);
            vc += __shfl_down_sync(0xffffffffu, vc, o);
        }
        if (tid == 0) {
            if (bx < 16) atomicAdd(&g_acc[0], (double)vo);
            atomicAdd(&g_acc[1], (double)vc);
        }
    }

    // ---------- per-image target processing (rides in bx==71 of each row) ----
    if (bx == BX - 1) {
        const int n = tid;

        float box_v = 0.0f, obj_v = 0.0f, cls_v = 0.0f;

        if (n < NT) {
            const float* t = tg + ((size_t)b * NT + n) * 5;
            const int   cls = (int)t[0];
            const float cx = t[1], cy = t[2];
            const int gi  = (int)(cx * (float)W);
            const int gj  = (int)(cy * (float)H);
            s_key[n] = ((gj * W + gi) << 7) | cls;
        }
        __syncthreads();

        if (n < NT) {
            const float* t = tg + ((size_t)b * NT + n) * 5;
            const int   cls = (int)t[0];
            const float cx = t[1], cy = t[2], w = t[3], h = t[4];
            const int   idx = s_key[n] >> 7;

            // set-scatter semantics: only the first target claiming a cell /
            // (cell,cls) contributes to the BCE correction term.
            bool first_obj = true, first_cls = true;
            for (int m = 0; m < n; m++) {
                if ((s_key[m] >> 7) == idx) {
                    first_obj = false;
                    if (s_key[m] == s_key[n]) first_cls = false;
                }
            }

            const float* pb = preds + (size_t)b * C * HW + idx;
            const float px = pb[0 * HW];
            const float py = pb[1 * HW];
            const float pw = pb[2 * HW];
            const float ph = pb[3 * HW];
            const float xo = pb[4 * HW];
            const float xc = pb[(size_t)(5 + cls) * HW];

            const float p1 = px - pw * 0.5f, p2 = py - ph * 0.5f;
            const float p3 = px + pw * 0.5f, p4v = py + ph * 0.5f;
            const float g1 = (cx - w * 0.5f) * (float)W, g2 = (cy - h * 0.5f) * (float)H;
            const float g3 = (cx + w * 0.5f) * (float)W, g4 = (cy + h * 0.5f) * (float)H;

            const float ix1 = fmaxf(p1, g1), iy1 = fmaxf(p2, g2);
            const float ix2 = fminf(p3, g3), iy2 = fminf(p4v, g4);
            const float inter = fmaxf(ix2 - ix1, 0.0f) * fmaxf(iy2 - iy1, 0.0f);
            const float a1 = (p3 - p1) * (p4v - p2);
            const float a2 = (g3 - g1) * (g4 - g2);
            const float iou = inter / (a1 + a2 - inter + 1e-7f);

            box_v = 1.0f - iou;
            obj_v = first_obj ? xo : 0.0f;
            cls_v = first_cls ? xc : 0.0f;
        }

#pragma unroll
        for (int o = 16; o > 0; o >>= 1) {
            box_v += __shfl_down_sync(0xffffffffu, box_v, o);
            obj_v += __shfl_down_sync(0xffffffffu, obj_v, o);
            cls_v += __shfl_down_sync(0xffffffffu, cls_v, o);
        }
        if (n < NT && (n & 31) == 0) {
            sh2[(n >> 5) * 3 + 0] = box_v;
            sh2[(n >> 5) * 3 + 1] = obj_v;
            sh2[(n >> 5) * 3 + 2] = cls_v;
        }
        __syncthreads();
        if (tid == 0) {
            atomicAdd(&g_acc[2], (double)(sh2[0] + sh2[3]));
            atomicAdd(&g_acc[3], (double)(sh2[1] + sh2[4]));
            atomicAdd(&g_acc[4], (double)(sh2[2] + sh2[5]));
        }
    }

    // ---------- last-block-done finalize ----------
    __syncthreads();
    if (tid == 0) {
        __threadfence();
        unsigned int ticket = atomicAdd(&g_done, 1u);
        if (ticket == BLOCKS - 1) {
            const double obj_loss = (g_acc[0] - g_acc[3]) / (double)HW;
            const double cls_loss = (g_acc[1] - g_acc[4]) / ((double)HW * (double)NC);
            const double box_loss = g_acc[2];
            out[0] = (float)(0.05 * box_loss + 1.0 * obj_loss + 0.5 * cls_loss);
            // reset state for the next launch / graph replay
            g_acc[0] = 0.0; g_acc[1] = 0.0; g_acc[2] = 0.0;
            g_acc[3] = 0.0; g_acc[4] = 0.0;
            __threadfence();
            g_done = 0u;
        }
    }
}

extern "C" void kernel_launch(void* const* d_in, const int* in_sizes, int n_in,
                              void* d_out, int out_size) {
    const float* preds   = (const float*)d_in[0];
    const float* targets = (const float*)d_in[1];
    float* out = (float*)d_out;

    dim3 grid(BX, B);
    fused_kernel<<<grid, THREADS>>>(preds, targets, out);
}

// round 9
// speedup vs baseline: 1.1364x; 1.1364x over previous
#include <cuda_runtime.h>

// Problem constants (fixed by the reference setup_inputs)
#define B   16
#define C   85
#define H   128
#define W   128
#define HW  (H * W)        // 16384
#define NT  64             // targets per image
#define NC  80             // num classes = C - 5
#define NCH 81             // channels 4..84 (obj + cls)

#define BLOCKS     1152                 // single wave; 1152*256*18 == TOTAL_F4 exactly
#define THREADS    256
#define ITERS      18
#define STRIDE_F4  (BLOCKS * THREADS)   // 294912

#define CH_F4      (HW / 4)             // 4096 float4 per channel
#define PER_B_F4   (NCH * CH_F4)        // 331776 float4 per batch image (ch 4..84)

#define LOG2E      1.4426950408889634f
#define LN2        0.6931471805599453

// Global accumulators + completion counter. Zero at module load; the last
// block of every launch resets them, so each launch / graph replay starts clean.
// [0] = sum log2(1+2^(x*log2e)) over obj channel   (softplus in log2 units)
// [1] = same over cls channels
// [2] = sum (1 - iou) box loss
// [3] = obj correction: sum of raw x_obj at unique assigned cells
// [4] = cls correction: sum of raw x_cls at unique (cell, cls) pairs
__device__ double        g_acc[5];
__device__ unsigned int  g_done;

__device__ __forceinline__ float ex2_approx(float x) {
    float r;
    asm("ex2.approx.f32 %0, %1;" : "=f"(r) : "f"(x));
    return r;
}
__device__ __forceinline__ float lg2_approx(float x) {
    float r;
    asm("lg2.approx.f32 %0, %1;" : "=f"(r) : "f"(x));
    return r;
}

// softplus(x) in log2 units: log2(1 + exp(x)) = log2(1 + 2^(x*log2e)).
// Per element: FMUL + MUFU.EX2 + FADD + MUFU.LG2. ln2 scaling deferred to finalize.
__device__ __forceinline__ float softplus_l2(float x) {
    return lg2_approx(1.0f + ex2_approx(x * LOG2E));
}

__global__ __launch_bounds__(THREADS) void fused_kernel(const float* __restrict__ preds,
                                                        const float* __restrict__ tg,
                                                        float* __restrict__ out) {
    const int bid = blockIdx.x;
    const int tid = threadIdx.x;
    const int gid = bid * THREADS + tid;

    __shared__ float sh[2 * THREADS];
    __shared__ float sh2[8];
    __shared__ int   s_key[NT];     // packed (idx<<7 | cls) per target

    // ---------- bulk softplus sweep: flat interleaved, one exact wave ----------
    const float4* __restrict__ p4 = reinterpret_cast<const float4*>(preds);

    float obj_acc = 0.0f;
    float cls_acc = 0.0f;

#pragma unroll
    for (int i = 0; i < ITERS; i++) {
        const int g    = gid + i * STRIDE_F4;              // flat idx in 81-ch space
        const int b    = g / PER_B_F4;                     // const-div -> mul/shift
        const int r    = g - b * PER_B_F4;                 // offset within 81-ch span
        // real addr: (b*C + 4)*CH_F4 + r  ==  g + (b+1)*HW (in f4 units)
        const int addr = g + (b + 1) * HW;
        const float4 v = p4[addr];
        const float  s = softplus_l2(v.x) + softplus_l2(v.y)
                       + softplus_l2(v.z) + softplus_l2(v.w);
        if (r < CH_F4) obj_acc += s;                       // channel 4 == obj
        else           cls_acc += s;
    }

    // block reduce both accumulators
    sh[tid]           = obj_acc;
    sh[tid + THREADS] = cls_acc;
    __syncthreads();
#pragma unroll
    for (int s = THREADS / 2; s > 32; s >>= 1) {
        if (tid < s) {
            sh[tid]           += sh[tid + s];
            sh[tid + THREADS] += sh[tid + THREADS + s];
        }
        __syncthreads();
    }
    if (tid < 32) {
        float vo = sh[tid] + sh[tid + 32];
        float vc = sh[tid + THREADS] + sh[tid + THREADS + 32];
#pragma unroll
        for (int o = 16; o > 0; o >>= 1) {
            vo += __shfl_down_sync(0xffffffffu, vo, o);
            vc += __shfl_down_sync(0xffffffffu, vc, o);
        }
        if (tid == 0) {
            atomicAdd(&g_acc[0], (double)vo);
            atomicAdd(&g_acc[1], (double)vc);
        }
    }

    // ---------- per-image target processing (rides in blocks 0..15) ----------
    if (bid < B) {
        const int b = bid;
        const int n = tid;

        float box_v = 0.0f, obj_v = 0.0f, cls_v = 0.0f;

        if (n < NT) {
            const float* t = tg + ((size_t)b * NT + n) * 5;
            const int   cls = (int)t[0];
            const float cx = t[1], cy = t[2];
            const int gi  = (int)(cx * (float)W);
            const int gj  = (int)(cy * (float)H);
            s_key[n] = ((gj * W + gi) << 7) | cls;
        }
        __syncthreads();

        if (n < NT) {
            const float* t = tg + ((size_t)b * NT + n) * 5;
            const int   cls = (int)t[0];
            const float cx = t[1], cy = t[2], w = t[3], h = t[4];
            const int   idx = s_key[n] >> 7;

            // set-scatter semantics: only the first target claiming a cell /
            // (cell,cls) contributes to the BCE correction term.
            bool first_obj = true, first_cls = true;
            for (int m = 0; m < n; m++) {
                if ((s_key[m] >> 7) == idx) {
                    first_obj = false;
                    if (s_key[m] == s_key[n]) first_cls = false;
                }
            }

            const float* pb = preds + (size_t)b * C * HW + idx;
            const float px = pb[0 * HW];
            const float py = pb[1 * HW];
            const float pw = pb[2 * HW];
            const float ph = pb[3 * HW];
            const float xo = pb[4 * HW];
            const float xc = pb[(size_t)(5 + cls) * HW];

            const float p1 = px - pw * 0.5f, p2 = py - ph * 0.5f;
            const float p3 = px + pw * 0.5f, p4v = py + ph * 0.5f;
            const float g1 = (cx - w * 0.5f) * (float)W, g2 = (cy - h * 0.5f) * (float)H;
            const float g3 = (cx + w * 0.5f) * (float)W, g4 = (cy + h * 0.5f) * (float)H;

            const float ix1 = fmaxf(p1, g1), iy1 = fmaxf(p2, g2);
            const float ix2 = fminf(p3, g3), iy2 = fminf(p4v, g4);
            const float inter = fmaxf(ix2 - ix1, 0.0f) * fmaxf(iy2 - iy1, 0.0f);
            const float a1 = (p3 - p1) * (p4v - p2);
            const float a2 = (g3 - g1) * (g4 - g2);
            const float iou = inter / (a1 + a2 - inter + 1e-7f);

            box_v = 1.0f - iou;
            obj_v = first_obj ? xo : 0.0f;
            cls_v = first_cls ? xc : 0.0f;
        }

#pragma unroll
        for (int o = 16; o > 0; o >>= 1) {
            box_v += __shfl_down_sync(0xffffffffu, box_v, o);
            obj_v += __shfl_down_sync(0xffffffffu, obj_v, o);
            cls_v += __shfl_down_sync(0xffffffffu, cls_v, o);
        }
        if (n < NT && (n & 31) == 0) {
            sh2[(n >> 5) * 3 + 0] = box_v;
            sh2[(n >> 5) * 3 + 1] = obj_v;
            sh2[(n >> 5) * 3 + 2] = cls_v;
        }
        __syncthreads();
        if (tid == 0) {
            atomicAdd(&g_acc[2], (double)(sh2[0] + sh2[3]));
            atomicAdd(&g_acc[3], (double)(sh2[1] + sh2[4]));
            atomicAdd(&g_acc[4], (double)(sh2[2] + sh2[5]));
        }
    }

    // ---------- last-block-done finalize ----------
    __syncthreads();
    if (tid == 0) {
        __threadfence();
        unsigned int ticket = atomicAdd(&g_done, 1u);
        if (ticket == BLOCKS - 1) {
            // g_acc[0], g_acc[1] are softplus sums in log2 units; scale by ln2.
            const double obj_loss = (LN2 * g_acc[0] - g_acc[3]) / (double)HW;
            const double cls_loss = (LN2 * g_acc[1] - g_acc[4]) / ((double)HW * (double)NC);
            const double box_loss = g_acc[2];
            out[0] = (float)(0.05 * box_loss + 1.0 * obj_loss + 0.5 * cls_loss);
            // reset state for the next launch / graph replay
            g_acc[0] = 0.0; g_acc[1] = 0.0; g_acc[2] = 0.0;
            g_acc[3] = 0.0; g_acc[4] = 0.0;
            __threadfence();
            g_done = 0u;
        }
    }
}

extern "C" void kernel_launch(void* const* d_in, const int* in_sizes, int n_in,
                              void* d_out, int out_size) {
    const float* preds   = (const float*)d_in[0];
    const float* targets = (const float*)d_in[1];
    float* out = (float*)d_out;

    fused_kernel<<<BLOCKS, THREADS>>>(preds, targets, out);
}